// round 14
// baseline (speedup 1.0000x reference)
#include <cuda_runtime.h>
#include <cuda_fp16.h>
#include <cstdint>

#define D        64
#define H        64
#define TPB      128
#define NW       4
#define TILE_M   128
#define CTAS_PER_SM 4
#define NMAXROW  100000

#define XSTRH    136             // halfs/row; 272 B stride (conflict-free, 16B aligned)
#define BSTRH    136

// dynamic smem layout (bytes)
#define SM_X      0
#define SM_XW     (32 * XSTRH * 2)                // 8704 B per warp (32 rows)
#define SM_X_SZ   (NW * SM_XW)                    // 34816
#define SM_B      (SM_X + SM_X_SZ)
#define SM_B_SZ   (H * BSTRH * 2)                 // 17408
#define SM_EA     (SM_B + SM_B_SZ)                // float4[32]: (w1c, w1c, b1, b1) pairs
#define SM_EB     (SM_EA + 512)                   // float2[32]: W2 pairs
#define SM_B2     (SM_EB + 256)
#define SM_IP     (SM_B2 + 16)                    // float[2][NW][32] inv-norm products
#define SM_TOTAL  (SM_IP + 1024)                  // 54032 B -> 4 CTAs/SM (216 KB)

__device__ __align__(16) __half  g_hc_h[NMAXROW * D];
__device__ __align__(16) __half  g_hp_h[NMAXROW * D];
__device__ __align__(16) __half  g_Bimg[H * BSTRH];
__device__ __align__(16) float4  g_EA[32];
__device__ __align__(16) float2  g_EB[32];
__device__ float g_invc[NMAXROW];
__device__ float g_invp[NMAXROW];

__global__ void prep_all(const float* __restrict__ hc, const float* __restrict__ hp,
                         const float* __restrict__ W1, const float* __restrict__ b1,
                         const float* __restrict__ W2, int n4c, int n4p) {
    int i = blockIdx.x * blockDim.x + threadIdx.x;
    if (i < n4c) {
        float4 v = ((const float4*)hc)[i];
        ((__half2*)g_hc_h)[2 * i]     = __floats2half2_rn(v.x, v.y);
        ((__half2*)g_hc_h)[2 * i + 1] = __floats2half2_rn(v.z, v.w);
    } else if (i < n4c + n4p) {
        int k = i - n4c;
        float4 v = ((const float4*)hp)[k];
        ((__half2*)g_hp_h)[2 * k]     = __floats2half2_rn(v.x, v.y);
        ((__half2*)g_hp_h)[2 * k + 1] = __floats2half2_rn(v.z, v.w);
    }
    if (i < H * BSTRH) {
        int n = i / BSTRH, k = i % BSTRH;
        g_Bimg[i] = __float2half_rn((k < 2 * D) ? W1[k * H + n] : 0.0f);
    }
    if (i < 32) {
        int n = 2 * i;
        g_EA[i] = make_float4(W1[2 * D * H + n], W1[2 * D * H + n + 1], b1[n], b1[n + 1]);
        g_EB[i] = make_float2(W2[n], W2[n + 1]);
    }
}

// inverse norms: 8 lanes per row, fp32
__global__ void norm_kernel(const float* __restrict__ hc, const float* __restrict__ hp,
                            int nc, int np) {
    int t = blockIdx.x * blockDim.x + threadIdx.x;
    int row = t >> 3, l8 = t & 7;
    const float* base; float* outp; int r;
    if (row < nc)            { base = hc; r = row;       outp = g_invc; }
    else if (row < nc + np)  { base = hp; r = row - nc;  outp = g_invp; }
    else return;
    const float4* p4 = (const float4*)(base + (size_t)r * D) + l8 * 2;
    float4 a = p4[0], b = p4[1];
    float s = a.x*a.x + a.y*a.y + a.z*a.z + a.w*a.w
            + b.x*b.x + b.y*b.y + b.z*b.z + b.w*b.w;
    s += __shfl_xor_sync(0xffffffffu, s, 1);
    s += __shfl_xor_sync(0xffffffffu, s, 2);
    s += __shfl_xor_sync(0xffffffffu, s, 4);
    if (l8 == 0) outp[r] = 1.0f / fmaxf(sqrtf(s), 1e-12f);
}

__device__ __forceinline__ uint32_t smem_u32(const void* p) {
    uint32_t a;
    asm("{ .reg .u64 t; cvta.to.shared.u64 t, %1; cvt.u32.u64 %0, t; }" : "=r"(a) : "l"(p));
    return a;
}
__device__ __forceinline__ void cp16(uint32_t saddr, const void* gaddr) {
    asm volatile("cp.async.cg.shared.global [%0], [%1], 16;" :: "r"(saddr), "l"(gaddr));
}
__device__ __forceinline__ void ldsm_x4(uint32_t& r0, uint32_t& r1, uint32_t& r2, uint32_t& r3,
                                        uint32_t addr) {
    asm volatile("ldmatrix.sync.aligned.m8n8.x4.shared.b16 {%0,%1,%2,%3}, [%4];"
                 : "=r"(r0), "=r"(r1), "=r"(r2), "=r"(r3) : "r"(addr));
}
__device__ __forceinline__ void mma_f16(float c[4],
                                        uint32_t a0, uint32_t a1, uint32_t a2, uint32_t a3,
                                        uint32_t b0, uint32_t b1) {
    asm volatile(
        "mma.sync.aligned.m16n8k16.row.col.f32.f16.f16.f32 "
        "{%0,%1,%2,%3}, {%4,%5,%6,%7}, {%8,%9}, {%0,%1,%2,%3};"
        : "+f"(c[0]), "+f"(c[1]), "+f"(c[2]), "+f"(c[3])
        : "r"(a0), "r"(a1), "r"(a2), "r"(a3), "r"(b0), "r"(b1));
}
__device__ __forceinline__ __half2 u2h(uint32_t u) { return *(__half2*)&u; }

__global__ __launch_bounds__(TPB, CTAS_PER_SM)
void edge_mlp_f16_kernel(const int*   __restrict__ src,
                         const int*   __restrict__ dst,
                         const float* __restrict__ b2,
                         float*       __restrict__ out,
                         int E, int ntiles)
{
    extern __shared__ char smem[];
    const uint32_t smem_base = smem_u32(smem);
    float4* sEA = (float4*)(smem + SM_EA);
    float2* sEB = (float2*)(smem + SM_EB);
    float*  sB2 = (float*)(smem + SM_B2);
    float*  sIP = (float*)(smem + SM_IP);        // [2][NW][32]

    const int tid   = threadIdx.x;
    const int wid   = tid >> 5;
    const int lane  = tid & 31;
    const int ngrid = gridDim.x;

    const uint32_t xw = smem_base + SM_X + (uint32_t)wid * SM_XW;

    // gather role constants
    const int el2   = lane >> 4;
    const int part  = (lane >> 3) & 1;
    const int chunk = lane & 7;

    // ---- stage-0 indices + inv norms ----
    int tile0 = blockIdx.x;
    int ec = tile0 * TILE_M + wid * 32 + lane; if (ec >= E) ec = E - 1;
    int sv = src[ec], tv = dst[ec];
    float ivc = g_invc[sv], ivp = g_invp[tv];

    // ---- B / epilogue-table staging (once) ----
    {
        const char* gB = (const char*)g_Bimg;
        uint32_t dB = smem_base + SM_B;
        #pragma unroll
        for (int i = 0; i < 9; ++i) {
            int c = i * TPB + tid;
            if (c < SM_B_SZ / 16) cp16(dB + (uint32_t)c * 16u, gB + c * 16);
        }
    }
    if (tid < 32) { sEA[tid] = g_EA[tid]; sEB[tid] = g_EB[tid]; }
    if (tid == 0) sB2[0] = b2[0];

    // ---- gather stage 0 ----
    #pragma unroll 8
    for (int i = 0; i < 16; ++i) {
        int ew = 2 * i + el2;
        int si = __shfl_sync(0xffffffffu, sv, ew);
        int ti = __shfl_sync(0xffffffffu, tv, ew);
        const __half* g = part ? g_hp_h + (size_t)ti * D + chunk * 8
                               : g_hc_h + (size_t)si * D + chunk * 8;
        cp16(xw + (uint32_t)ew * (XSTRH * 2u) + (uint32_t)(part * 128 + chunk * 16), g);
    }
    asm volatile("cp.async.commit_group;" ::: "memory");

    // stage-0 inv products -> sIP buffer 0
    sIP[(0 * NW + wid) * 32 + lane] = ivc * ivp;

    // ---- prefetch stage-1 indices ----
    {
        int bb = (tile0 + ngrid) * TILE_M + wid * 32 + lane;
        int ecl = (bb < E) ? bb : (E - 1);
        sv = src[ecl]; tv = dst[ecl];
    }

    asm volatile("cp.async.wait_group 0;" ::: "memory");
    __syncthreads();                 // B/tables/sIP visible; only CTA-wide barrier

    // ---- ldmatrix addresses ----
    const int j = lane >> 3;
    const int r = lane & 7;
    const uint32_t aA0 = xw + (uint32_t)(((j & 1) * 8 + r) * (XSTRH * 2)) + (uint32_t)(j >> 1) * 16u;
    const uint32_t aA1 = aA0 + 16u * (XSTRH * 2u);
    uint32_t aB[4];
    #pragma unroll
    for (int p = 0; p < 4; ++p)
        aB[p] = smem_base + SM_B
              + (uint32_t)((p * 16 + r + (j >> 1) * 8) * (BSTRH * 2))
              + (uint32_t)(j & 1) * 16u;

    const int qrow  = lane >> 2;
    const int qlane = lane & 3;
    const float bias2v = sB2[0];
    int pbuf = 0;

    // =================== stage loop ===================
    for (int tile = tile0; tile < ntiles; tile += ngrid) {
        float acc[2][8][4];
        #pragma unroll
        for (int mt = 0; mt < 2; ++mt)
            #pragma unroll
            for (int nt = 0; nt < 8; ++nt)
                #pragma unroll
                for (int c = 0; c < 4; ++c) acc[mt][nt][c] = 0.f;

        __half2 cdp[2][2];
        #pragma unroll
        for (int mt = 0; mt < 2; ++mt) {
            cdp[mt][0] = __float2half2_rn(0.f);
            cdp[mt][1] = __float2half2_rn(0.f);
        }

        // ---- fused k-loop: pairs (ks, ks+4) = (head cols, tail cols) ----
        #pragma unroll
        for (int ksp = 0; ksp < 4; ++ksp) {
            const uint32_t ko  = (uint32_t)ksp * 32u;
            const uint32_t ko2 = ko + 128u;

            uint32_t ah[2][4], at[2][4];
            ldsm_x4(ah[0][0], ah[0][1], ah[0][2], ah[0][3], aA0 + ko);
            ldsm_x4(ah[1][0], ah[1][1], ah[1][2], ah[1][3], aA1 + ko);
            ldsm_x4(at[0][0], at[0][1], at[0][2], at[0][3], aA0 + ko2);
            ldsm_x4(at[1][0], at[1][1], at[1][2], at[1][3], aA1 + ko2);

            if (ksp == 0) {
                // inv norms for next stage's edges (sv/tv currently = s+1)
                ivc = g_invc[sv]; ivp = g_invp[tv];
            }
            if (ksp == 3) {
                // all X reads of this stage issued -> safe to refill buffer
                if (tile + ngrid < ntiles) {
                    #pragma unroll 8
                    for (int i = 0; i < 16; ++i) {
                        int ew = 2 * i + el2;
                        int si = __shfl_sync(0xffffffffu, sv, ew);
                        int ti = __shfl_sync(0xffffffffu, tv, ew);
                        const __half* g = part ? g_hp_h + (size_t)ti * D + chunk * 8
                                               : g_hc_h + (size_t)si * D + chunk * 8;
                        cp16(xw + (uint32_t)ew * (XSTRH * 2u) + (uint32_t)(part * 128 + chunk * 16), g);
                    }
                }
                asm volatile("cp.async.commit_group;" ::: "memory");
                // next stage's inv products into the other sIP buffer
                sIP[((pbuf ^ 1) * NW + wid) * 32 + lane] = ivc * ivp;
                // prefetch indices for stage after next
                int bb = (tile + 2 * ngrid) * TILE_M + wid * 32 + lane;
                int ecl = (bb < E) ? bb : (E - 1);
                sv = src[ecl]; tv = dst[ecl];
            }

            // dot partials only (norms precomputed)
            #pragma unroll
            for (int mt = 0; mt < 2; ++mt) {
                cdp[mt][0] = __hfma2(u2h(ah[mt][0]), u2h(at[mt][0]), cdp[mt][0]);
                cdp[mt][0] = __hfma2(u2h(ah[mt][2]), u2h(at[mt][2]), cdp[mt][0]);
                cdp[mt][1] = __hfma2(u2h(ah[mt][1]), u2h(at[mt][1]), cdp[mt][1]);
                cdp[mt][1] = __hfma2(u2h(ah[mt][3]), u2h(at[mt][3]), cdp[mt][1]);
            }

            // B fragments + MMAs: head k-step
            {
                uint32_t bf[8][2];
                #pragma unroll
                for (int p = 0; p < 4; ++p) {
                    uint32_t r0, r1, r2, r3;
                    ldsm_x4(r0, r1, r2, r3, aB[p] + ko);
                    bf[2*p][0] = r0;   bf[2*p][1] = r1;
                    bf[2*p+1][0] = r2; bf[2*p+1][1] = r3;
                }
                #pragma unroll
                for (int nt = 0; nt < 8; ++nt) {
                    mma_f16(acc[0][nt], ah[0][0], ah[0][1], ah[0][2], ah[0][3], bf[nt][0], bf[nt][1]);
                    mma_f16(acc[1][nt], ah[1][0], ah[1][1], ah[1][2], ah[1][3], bf[nt][0], bf[nt][1]);
                }
            }
            // tail k-step
            {
                uint32_t bf[8][2];
                #pragma unroll
                for (int p = 0; p < 4; ++p) {
                    uint32_t r0, r1, r2, r3;
                    ldsm_x4(r0, r1, r2, r3, aB[p] + ko2);
                    bf[2*p][0] = r0;   bf[2*p][1] = r1;
                    bf[2*p+1][0] = r2; bf[2*p+1][1] = r3;
                }
                #pragma unroll
                for (int nt = 0; nt < 8; ++nt) {
                    mma_f16(acc[0][nt], at[0][0], at[0][1], at[0][2], at[0][3], bf[nt][0], bf[nt][1]);
                    mma_f16(acc[1][nt], at[1][0], at[1][1], at[1][2], at[1][3], bf[nt][0], bf[nt][1]);
                }
            }
        }

        // ---- finalize cosines: dp butterfly x inv-norm product ----
        float cos4[2][2];
        #pragma unroll
        for (int mt = 0; mt < 2; ++mt)
            #pragma unroll
            for (int h = 0; h < 2; ++h) {
                float2 c = __half22float2(cdp[mt][h]);
                float dp = c.x + c.y;
                dp += __shfl_xor_sync(0xffffffffu, dp, 1);
                dp += __shfl_xor_sync(0xffffffffu, dp, 2);
                float ip = sIP[(pbuf * NW + wid) * 32 + (mt * 16 + h * 8 + qrow)];
                cos4[mt][h] = dp * ip;
            }

        // ---- epilogue: +cos*w1c + b1, relu, dot W2, sigmoid ----
        {
            float zz[2][2] = {{0.f, 0.f}, {0.f, 0.f}};
            #pragma unroll
            for (int nt = 0; nt < 8; ++nt) {
                float4 ea = sEA[nt * 4 + qlane];
                float2 eb = sEB[nt * 4 + qlane];
                #pragma unroll
                for (int mt = 0; mt < 2; ++mt)
                    #pragma unroll
                    for (int rr = 0; rr < 2; ++rr) {
                        float cR = cos4[mt][rr];
                        float v0 = acc[mt][nt][2*rr]     + fmaf(cR, ea.x, ea.z);
                        float v1 = acc[mt][nt][2*rr + 1] + fmaf(cR, ea.y, ea.w);
                        zz[mt][rr] = fmaf(fmaxf(v0, 0.f), eb.x, zz[mt][rr]);
                        zz[mt][rr] = fmaf(fmaxf(v1, 0.f), eb.y, zz[mt][rr]);
                    }
            }
            const int ebase = tile * TILE_M + wid * 32;
            #pragma unroll
            for (int mt = 0; mt < 2; ++mt)
                #pragma unroll
                for (int rr = 0; rr < 2; ++rr) {
                    float z = zz[mt][rr];
                    z += __shfl_xor_sync(0xffffffffu, z, 1);
                    z += __shfl_xor_sync(0xffffffffu, z, 2);
                    if (qlane == 0) {
                        int eo = ebase + mt * 16 + rr * 8 + qrow;
                        if (eo < E) {
                            float ez = __expf(-(z + bias2v));
                            out[eo] = __fdividef(1.0f, 1.0f + ez);
                        }
                    }
                }
        }

        asm volatile("cp.async.wait_group 0;" ::: "memory");
        __syncwarp();
        pbuf ^= 1;
    }
}

extern "C" void kernel_launch(void* const* d_in, const int* in_sizes, int n_in,
                              void* d_out, int out_size)
{
    const float* hc  = (const float*)d_in[0];
    const float* hp  = (const float*)d_in[1];
    const int*   src = (const int*)  d_in[2];
    const int*   dst = (const int*)  d_in[3];
    const float* W1  = (const float*)d_in[4];
    const float* b1  = (const float*)d_in[5];
    const float* W2  = (const float*)d_in[6];
    const float* b2  = (const float*)d_in[7];
    float* out = (float*)d_out;

    static int nsm = 0;
    if (!nsm) {
        cudaDeviceGetAttribute(&nsm, cudaDevAttrMultiProcessorCount, 0);
        cudaFuncSetAttribute(edge_mlp_f16_kernel,
                             cudaFuncAttributeMaxDynamicSharedMemorySize, SM_TOTAL);
    }

    int E   = in_sizes[2];
    int nc  = in_sizes[0] / D;
    int np  = in_sizes[1] / D;
    int n4c = in_sizes[0] / 4;
    int n4p = in_sizes[1] / 4;
    int n4  = n4c + n4p;

    prep_all<<<(n4 + 255) / 256, 256>>>(hc, hp, W1, b1, W2, n4c, n4p);
    norm_kernel<<<((nc + np) * 8 + 255) / 256, 256>>>(hc, hp, nc, np);

    int ntiles = (E + TILE_M - 1) / TILE_M;
    int ngrid  = nsm * CTAS_PER_SM;
    if (ngrid > ntiles) ngrid = ntiles;
    edge_mlp_f16_kernel<<<ngrid, TPB, SM_TOTAL>>>(src, dst, b2, out, E, ntiles);
}

// round 15
// speedup vs baseline: 1.2066x; 1.2066x over previous
#include <cuda_runtime.h>
#include <cuda_fp16.h>
#include <cstdint>

#define D        64
#define H        64
#define TPB      128
#define NW       4
#define TILE_M   128
#define CTAS_PER_SM 3
#define NMAXROW  100000

#define XSTRH    136             // halfs/row; 272 B stride (conflict-free, 16B aligned)
#define BSTRH    136

// dynamic smem layout (bytes)
#define SM_X      0
#define SM_XW     (32 * XSTRH * 2)                // 8704 B per warp (32 rows)
#define SM_X_SZ   (NW * SM_XW)                    // 34816
#define SM_B      (SM_X + SM_X_SZ)
#define SM_B_SZ   (H * BSTRH * 2)                 // 17408
#define SM_EA     (SM_B + SM_B_SZ)                // float4[32]: (w1c, w1c, b1, b1) pairs
#define SM_EB     (SM_EA + 512)                   // float2[32]: W2 pairs
#define SM_B2     (SM_EB + 256)
#define SM_IP     (SM_B2 + 16)                    // float[2][NW][32] inv-norm products
#define SM_TOTAL  (SM_IP + 1024)                  // ~54 KB -> 3 CTAs/SM

__device__ __align__(16) __half  g_hc_h[NMAXROW * D];
__device__ __align__(16) __half  g_hp_h[NMAXROW * D];
__device__ __align__(16) __half  g_Bimg[H * BSTRH];
__device__ __align__(16) float4  g_EA[32];
__device__ __align__(16) float2  g_EB[32];
__device__ float g_invc[NMAXROW];
__device__ float g_invp[NMAXROW];

// one pass: fp32->fp16 table conversion + fused inv-norm (8 threads/row, 32B each)
__global__ void prep_all(const float* __restrict__ hc, const float* __restrict__ hp,
                         const float* __restrict__ W1, const float* __restrict__ b1,
                         const float* __restrict__ W2, int nc, int np) {
    int t = blockIdx.x * blockDim.x + threadIdx.x;
    int row = t >> 3;
    int l8  = t & 7;
    int nrows = nc + np;
    if (row < nrows) {
        const bool isC = (row < nc);
        int r = isC ? row : row - nc;
        const float4* p4 = (const float4*)((isC ? hc : hp) + (size_t)r * D) + l8 * 2;
        float4 a = p4[0], b = p4[1];
        uint4 w;
        __half2* wp = (__half2*)&w;
        wp[0] = __floats2half2_rn(a.x, a.y);
        wp[1] = __floats2half2_rn(a.z, a.w);
        wp[2] = __floats2half2_rn(b.x, b.y);
        wp[3] = __floats2half2_rn(b.z, b.w);
        *(uint4*)((isC ? g_hc_h : g_hp_h) + (size_t)r * D + l8 * 8) = w;
        float s = a.x*a.x + a.y*a.y + a.z*a.z + a.w*a.w
                + b.x*b.x + b.y*b.y + b.z*b.z + b.w*b.w;
        s += __shfl_xor_sync(0xffffffffu, s, 1);
        s += __shfl_xor_sync(0xffffffffu, s, 2);
        s += __shfl_xor_sync(0xffffffffu, s, 4);
        if (l8 == 0) {
            float iv = 1.0f / fmaxf(sqrtf(s), 1e-12f);
            if (isC) g_invc[r] = iv; else g_invp[r] = iv;
        }
    }
    if (t < H * BSTRH) {
        int n = t / BSTRH, k = t % BSTRH;
        g_Bimg[t] = __float2half_rn((k < 2 * D) ? W1[k * H + n] : 0.0f);
    }
    if (t < 32) {
        int n = 2 * t;
        g_EA[t] = make_float4(W1[2 * D * H + n], W1[2 * D * H + n + 1], b1[n], b1[n + 1]);
        g_EB[t] = make_float2(W2[n], W2[n + 1]);
    }
}

__device__ __forceinline__ uint32_t smem_u32(const void* p) {
    uint32_t a;
    asm("{ .reg .u64 t; cvta.to.shared.u64 t, %1; cvt.u32.u64 %0, t; }" : "=r"(a) : "l"(p));
    return a;
}
__device__ __forceinline__ void cp16(uint32_t saddr, const void* gaddr) {
    asm volatile("cp.async.cg.shared.global [%0], [%1], 16;" :: "r"(saddr), "l"(gaddr));
}
__device__ __forceinline__ void ldsm_x4(uint32_t& r0, uint32_t& r1, uint32_t& r2, uint32_t& r3,
                                        uint32_t addr) {
    asm volatile("ldmatrix.sync.aligned.m8n8.x4.shared.b16 {%0,%1,%2,%3}, [%4];"
                 : "=r"(r0), "=r"(r1), "=r"(r2), "=r"(r3) : "r"(addr));
}
__device__ __forceinline__ void mma_f16(float c[4],
                                        uint32_t a0, uint32_t a1, uint32_t a2, uint32_t a3,
                                        uint32_t b0, uint32_t b1) {
    asm volatile(
        "mma.sync.aligned.m16n8k16.row.col.f32.f16.f16.f32 "
        "{%0,%1,%2,%3}, {%4,%5,%6,%7}, {%8,%9}, {%0,%1,%2,%3};"
        : "+f"(c[0]), "+f"(c[1]), "+f"(c[2]), "+f"(c[3])
        : "r"(a0), "r"(a1), "r"(a2), "r"(a3), "r"(b0), "r"(b1));
}
__device__ __forceinline__ __half2 u2h(uint32_t u) { return *(__half2*)&u; }

__global__ __launch_bounds__(TPB, CTAS_PER_SM)
void edge_mlp_f16_kernel(const int*   __restrict__ src,
                         const int*   __restrict__ dst,
                         const float* __restrict__ b2,
                         float*       __restrict__ out,
                         int E, int ntiles)
{
    extern __shared__ char smem[];
    const uint32_t smem_base = smem_u32(smem);
    float4* sEA = (float4*)(smem + SM_EA);
    float2* sEB = (float2*)(smem + SM_EB);
    float*  sB2 = (float*)(smem + SM_B2);
    float*  sIP = (float*)(smem + SM_IP);        // [2][NW][32]

    const int tid   = threadIdx.x;
    const int wid   = tid >> 5;
    const int lane  = tid & 31;
    const int ngrid = gridDim.x;

    const uint32_t xw = smem_base + SM_X + (uint32_t)wid * SM_XW;

    const int el2   = lane >> 4;
    const int part  = (lane >> 3) & 1;
    const int chunk = lane & 7;

    // ---- stage-0 indices + inv norms ----
    int tile0 = blockIdx.x;
    int ec = tile0 * TILE_M + wid * 32 + lane; if (ec >= E) ec = E - 1;
    int sv = src[ec], tv = dst[ec];
    float ivc = g_invc[sv], ivp = g_invp[tv];

    // ---- B / epilogue-table staging (once) ----
    {
        const char* gB = (const char*)g_Bimg;
        uint32_t dB = smem_base + SM_B;
        #pragma unroll
        for (int i = 0; i < 9; ++i) {
            int c = i * TPB + tid;
            if (c < SM_B_SZ / 16) cp16(dB + (uint32_t)c * 16u, gB + c * 16);
        }
    }
    if (tid < 32) { sEA[tid] = g_EA[tid]; sEB[tid] = g_EB[tid]; }
    if (tid == 0) sB2[0] = b2[0];

    // ---- gather stage 0 ----
    #pragma unroll 8
    for (int i = 0; i < 16; ++i) {
        int ew = 2 * i + el2;
        int si = __shfl_sync(0xffffffffu, sv, ew);
        int ti = __shfl_sync(0xffffffffu, tv, ew);
        const __half* g = part ? g_hp_h + (size_t)ti * D + chunk * 8
                               : g_hc_h + (size_t)si * D + chunk * 8;
        cp16(xw + (uint32_t)ew * (XSTRH * 2u) + (uint32_t)(part * 128 + chunk * 16), g);
    }
    asm volatile("cp.async.commit_group;" ::: "memory");

    sIP[(0 * NW + wid) * 32 + lane] = ivc * ivp;

    // ---- prefetch stage-1 indices ----
    {
        int bb = (tile0 + ngrid) * TILE_M + wid * 32 + lane;
        int ecl = (bb < E) ? bb : (E - 1);
        sv = src[ecl]; tv = dst[ecl];
    }

    asm volatile("cp.async.wait_group 0;" ::: "memory");
    __syncthreads();

    // ---- ldmatrix addresses ----
    const int j = lane >> 3;
    const int r = lane & 7;
    const uint32_t aA0 = xw + (uint32_t)(((j & 1) * 8 + r) * (XSTRH * 2)) + (uint32_t)(j >> 1) * 16u;
    const uint32_t aA1 = aA0 + 16u * (XSTRH * 2u);
    uint32_t aB[4];
    #pragma unroll
    for (int p = 0; p < 4; ++p)
        aB[p] = smem_base + SM_B
              + (uint32_t)((p * 16 + r + (j >> 1) * 8) * (BSTRH * 2))
              + (uint32_t)(j & 1) * 16u;

    const int qrow  = lane >> 2;
    const int qlane = lane & 3;
    const float bias2v = sB2[0];
    int pbuf = 0;

    // =================== stage loop ===================
    for (int tile = tile0; tile < ntiles; tile += ngrid) {
        float acc[2][8][4];
        #pragma unroll
        for (int mt = 0; mt < 2; ++mt)
            #pragma unroll
            for (int nt = 0; nt < 8; ++nt)
                #pragma unroll
                for (int c = 0; c < 4; ++c) acc[mt][nt][c] = 0.f;

        __half2 cdp[2][2];
        #pragma unroll
        for (int mt = 0; mt < 2; ++mt) {
            cdp[mt][0] = __float2half2_rn(0.f);
            cdp[mt][1] = __float2half2_rn(0.f);
        }

        // ---- fused k-loop: pairs (ks, ks+4) = (head cols, tail cols) ----
        #pragma unroll
        for (int ksp = 0; ksp < 4; ++ksp) {
            const uint32_t ko  = (uint32_t)ksp * 32u;
            const uint32_t ko2 = ko + 128u;

            uint32_t ah[2][4], at[2][4];
            ldsm_x4(ah[0][0], ah[0][1], ah[0][2], ah[0][3], aA0 + ko);
            ldsm_x4(ah[1][0], ah[1][1], ah[1][2], ah[1][3], aA1 + ko);
            ldsm_x4(at[0][0], at[0][1], at[0][2], at[0][3], aA0 + ko2);
            ldsm_x4(at[1][0], at[1][1], at[1][2], at[1][3], aA1 + ko2);

            if (ksp == 0) {
                ivc = g_invc[sv]; ivp = g_invp[tv];   // next stage's norms
            }
            if (ksp == 3) {
                if (tile + ngrid < ntiles) {
                    #pragma unroll 8
                    for (int i = 0; i < 16; ++i) {
                        int ew = 2 * i + el2;
                        int si = __shfl_sync(0xffffffffu, sv, ew);
                        int ti = __shfl_sync(0xffffffffu, tv, ew);
                        const __half* g = part ? g_hp_h + (size_t)ti * D + chunk * 8
                                               : g_hc_h + (size_t)si * D + chunk * 8;
                        cp16(xw + (uint32_t)ew * (XSTRH * 2u) + (uint32_t)(part * 128 + chunk * 16), g);
                    }
                }
                asm volatile("cp.async.commit_group;" ::: "memory");
                sIP[((pbuf ^ 1) * NW + wid) * 32 + lane] = ivc * ivp;
                int bb = (tile + 2 * ngrid) * TILE_M + wid * 32 + lane;
                int ecl = (bb < E) ? bb : (E - 1);
                sv = src[ecl]; tv = dst[ecl];
            }

            // dot partials only (norms precomputed)
            #pragma unroll
            for (int mt = 0; mt < 2; ++mt) {
                cdp[mt][0] = __hfma2(u2h(ah[mt][0]), u2h(at[mt][0]), cdp[mt][0]);
                cdp[mt][0] = __hfma2(u2h(ah[mt][2]), u2h(at[mt][2]), cdp[mt][0]);
                cdp[mt][1] = __hfma2(u2h(ah[mt][1]), u2h(at[mt][1]), cdp[mt][1]);
                cdp[mt][1] = __hfma2(u2h(ah[mt][3]), u2h(at[mt][3]), cdp[mt][1]);
            }

            // B fragments + MMAs: head k-step
            {
                uint32_t bf[8][2];
                #pragma unroll
                for (int p = 0; p < 4; ++p) {
                    uint32_t r0, r1, r2, r3;
                    ldsm_x4(r0, r1, r2, r3, aB[p] + ko);
                    bf[2*p][0] = r0;   bf[2*p][1] = r1;
                    bf[2*p+1][0] = r2; bf[2*p+1][1] = r3;
                }
                #pragma unroll
                for (int nt = 0; nt < 8; ++nt) {
                    mma_f16(acc[0][nt], ah[0][0], ah[0][1], ah[0][2], ah[0][3], bf[nt][0], bf[nt][1]);
                    mma_f16(acc[1][nt], ah[1][0], ah[1][1], ah[1][2], ah[1][3], bf[nt][0], bf[nt][1]);
                }
            }
            // tail k-step
            {
                uint32_t bf[8][2];
                #pragma unroll
                for (int p = 0; p < 4; ++p) {
                    uint32_t r0, r1, r2, r3;
                    ldsm_x4(r0, r1, r2, r3, aB[p] + ko2);
                    bf[2*p][0] = r0;   bf[2*p][1] = r1;
                    bf[2*p+1][0] = r2; bf[2*p+1][1] = r3;
                }
                #pragma unroll
                for (int nt = 0; nt < 8; ++nt) {
                    mma_f16(acc[0][nt], at[0][0], at[0][1], at[0][2], at[0][3], bf[nt][0], bf[nt][1]);
                    mma_f16(acc[1][nt], at[1][0], at[1][1], at[1][2], at[1][3], bf[nt][0], bf[nt][1]);
                }
            }
        }

        // ---- finalize cosines: dp butterfly x inv-norm product ----
        float cos4[2][2];
        #pragma unroll
        for (int mt = 0; mt < 2; ++mt)
            #pragma unroll
            for (int h = 0; h < 2; ++h) {
                float2 c = __half22float2(cdp[mt][h]);
                float dp = c.x + c.y;
                dp += __shfl_xor_sync(0xffffffffu, dp, 1);
                dp += __shfl_xor_sync(0xffffffffu, dp, 2);
                float ip = sIP[(pbuf * NW + wid) * 32 + (mt * 16 + h * 8 + qrow)];
                cos4[mt][h] = dp * ip;
            }

        // ---- epilogue: +cos*w1c + b1, relu, dot W2, sigmoid ----
        {
            float zz[2][2] = {{0.f, 0.f}, {0.f, 0.f}};
            #pragma unroll
            for (int nt = 0; nt < 8; ++nt) {
                float4 ea = sEA[nt * 4 + qlane];
                float2 eb = sEB[nt * 4 + qlane];
                #pragma unroll
                for (int mt = 0; mt < 2; ++mt)
                    #pragma unroll
                    for (int rr = 0; rr < 2; ++rr) {
                        float cR = cos4[mt][rr];
                        float v0 = acc[mt][nt][2*rr]     + fmaf(cR, ea.x, ea.z);
                        float v1 = acc[mt][nt][2*rr + 1] + fmaf(cR, ea.y, ea.w);
                        zz[mt][rr] = fmaf(fmaxf(v0, 0.f), eb.x, zz[mt][rr]);
                        zz[mt][rr] = fmaf(fmaxf(v1, 0.f), eb.y, zz[mt][rr]);
                    }
            }
            const int ebase = tile * TILE_M + wid * 32;
            #pragma unroll
            for (int mt = 0; mt < 2; ++mt)
                #pragma unroll
                for (int rr = 0; rr < 2; ++rr) {
                    float z = zz[mt][rr];
                    z += __shfl_xor_sync(0xffffffffu, z, 1);
                    z += __shfl_xor_sync(0xffffffffu, z, 2);
                    if (qlane == 0) {
                        int eo = ebase + mt * 16 + rr * 8 + qrow;
                        if (eo < E) {
                            float ez = __expf(-(z + bias2v));
                            out[eo] = __fdividef(1.0f, 1.0f + ez);
                        }
                    }
                }
        }

        asm volatile("cp.async.wait_group 0;" ::: "memory");
        __syncwarp();
        pbuf ^= 1;
    }
}

extern "C" void kernel_launch(void* const* d_in, const int* in_sizes, int n_in,
                              void* d_out, int out_size)
{
    const float* hc  = (const float*)d_in[0];
    const float* hp  = (const float*)d_in[1];
    const int*   src = (const int*)  d_in[2];
    const int*   dst = (const int*)  d_in[3];
    const float* W1  = (const float*)d_in[4];
    const float* b1  = (const float*)d_in[5];
    const float* W2  = (const float*)d_in[6];
    const float* b2  = (const float*)d_in[7];
    float* out = (float*)d_out;

    static int nsm = 0;
    if (!nsm) {
        cudaDeviceGetAttribute(&nsm, cudaDevAttrMultiProcessorCount, 0);
        cudaFuncSetAttribute(edge_mlp_f16_kernel,
                             cudaFuncAttributeMaxDynamicSharedMemorySize, SM_TOTAL);
    }

    int E  = in_sizes[2];
    int nc = in_sizes[0] / D;
    int np = in_sizes[1] / D;

    int pthreads = (nc + np) * 8;
    if (pthreads < H * BSTRH) pthreads = H * BSTRH;
    prep_all<<<(pthreads + 255) / 256, 256>>>(hc, hp, W1, b1, W2, nc, np);

    int ntiles = (E + TILE_M - 1) / TILE_M;
    int ngrid  = nsm * CTAS_PER_SM;
    if (ngrid > ntiles) ngrid = ntiles;
    edge_mlp_f16_kernel<<<ngrid, TPB, SM_TOTAL>>>(src, dst, b2, out, E, ntiles);
}